// round 1
// baseline (speedup 1.0000x reference)
#include <cuda_runtime.h>
#include <math.h>
#include <stdint.h>

#define T_TOK 2048
#define H_DIM 2048
#define I_DIM 2048
#define E_NUM 16
#define TOPK  4
#define ROWS  (T_TOK*TOPK)   // 8192 grouped rows

// ---------------- scratch (static device globals; no allocation) ----------------
__device__ float g_tnorm[(size_t)T_TOK * H_DIM];     // 16 MB  normalized activations
__device__ float g_h1[(size_t)ROWS * I_DIM];         // 64 MB  swiglu outputs (grouped rows)
__device__ float g_h2[(size_t)ROWS * H_DIM];         // 64 MB  expert outputs * weight
__device__ int   g_cnt[E_NUM];
__device__ int   g_cnt2[E_NUM];
__device__ int   g_off[E_NUM];
__device__ int   g_rowtok[ROWS];                     // grouped row -> token
__device__ float g_roww[ROWS];                       // grouped row -> routing weight
__device__ int   g_tokrows[T_TOK * TOPK];            // token,k -> grouped row
__device__ int   g_topidx[T_TOK * TOPK];
__device__ float g_topw[T_TOK * TOPK];

// ---------------- packed fp32x2 helpers (sm_100+ full-rate FMA path) ----------------
__device__ __forceinline__ unsigned long long pk2(float x, float y) {
    unsigned long long r;
    asm("mov.b64 %0, {%1,%2};" : "=l"(r) : "f"(x), "f"(y));
    return r;
}
__device__ __forceinline__ void upk2(unsigned long long v, float& x, float& y) {
    asm("mov.b64 {%0,%1}, %2;" : "=f"(x), "=f"(y) : "l"(v));
}
__device__ __forceinline__ unsigned long long fma2(unsigned long long a,
                                                   unsigned long long b,
                                                   unsigned long long c) {
    unsigned long long d;
    asm("fma.rn.f32x2 %0, %1, %2, %3;" : "=l"(d) : "l"(a), "l"(b), "l"(c));
    return d;
}

// ---------------- 0: init counters ----------------
__global__ void init_kernel() {
    int i = threadIdx.x;
    if (i < E_NUM) { g_cnt[i] = 0; g_cnt2[i] = 0; }
}

// ---------------- 1: fused RMSNorm + router (one block per token) ----------------
__global__ __launch_bounds__(256) void rms_router_kernel(
    const float* __restrict__ x, const float* __restrict__ scale,
    const float* __restrict__ gk, const float* __restrict__ gb)
{
    int t = blockIdx.x;
    int tid = threadIdx.x;                 // 256 threads, 8 h-elems each
    const float* xr = x + (size_t)t * H_DIM;

    float4 v0 = *(const float4*)(xr + tid * 8);
    float4 v1 = *(const float4*)(xr + tid * 8 + 4);
    float ss = v0.x*v0.x + v0.y*v0.y + v0.z*v0.z + v0.w*v0.w
             + v1.x*v1.x + v1.y*v1.y + v1.z*v1.z + v1.w*v1.w;

    // deterministic block reduction
    #pragma unroll
    for (int o = 16; o > 0; o >>= 1) ss += __shfl_down_sync(0xffffffffu, ss, o);
    __shared__ float warpsum[8];
    __shared__ float s_r;
    if ((tid & 31) == 0) warpsum[tid >> 5] = ss;
    __syncthreads();
    if (tid == 0) {
        float tot = 0.f;
        #pragma unroll
        for (int w = 0; w < 8; w++) tot += warpsum[w];
        s_r = 1.0f / sqrtf(tot / (float)H_DIM + 1e-5f);
    }
    __syncthreads();
    float r = s_r;

    float4 sc0 = *(const float4*)(scale + tid * 8);
    float4 sc1 = *(const float4*)(scale + tid * 8 + 4);
    float tn[8];
    tn[0] = v0.x * r * sc0.x; tn[1] = v0.y * r * sc0.y;
    tn[2] = v0.z * r * sc0.z; tn[3] = v0.w * r * sc0.w;
    tn[4] = v1.x * r * sc1.x; tn[5] = v1.y * r * sc1.y;
    tn[6] = v1.z * r * sc1.z; tn[7] = v1.w * r * sc1.w;

    float* tr = g_tnorm + (size_t)t * H_DIM + tid * 8;
    *(float4*)(tr)     = make_float4(tn[0], tn[1], tn[2], tn[3]);
    *(float4*)(tr + 4) = make_float4(tn[4], tn[5], tn[6], tn[7]);

    // router partials: g[e] += tn[h] * gk[h*16+e]
    float ge[E_NUM];
    #pragma unroll
    for (int e = 0; e < E_NUM; e++) ge[e] = 0.f;
    #pragma unroll
    for (int u = 0; u < 8; u++) {
        const float4* wrow = (const float4*)(gk + (size_t)(tid * 8 + u) * E_NUM);
        float tv = tn[u];
        float4 a = wrow[0], b = wrow[1], c = wrow[2], d = wrow[3];
        ge[0]  += tv * a.x; ge[1]  += tv * a.y; ge[2]  += tv * a.z; ge[3]  += tv * a.w;
        ge[4]  += tv * b.x; ge[5]  += tv * b.y; ge[6]  += tv * b.z; ge[7]  += tv * b.w;
        ge[8]  += tv * c.x; ge[9]  += tv * c.y; ge[10] += tv * c.z; ge[11] += tv * c.w;
        ge[12] += tv * d.x; ge[13] += tv * d.y; ge[14] += tv * d.z; ge[15] += tv * d.w;
    }
    // deterministic reduction of 16 values
    #pragma unroll
    for (int o = 16; o > 0; o >>= 1) {
        #pragma unroll
        for (int e = 0; e < E_NUM; e++) ge[e] += __shfl_down_sync(0xffffffffu, ge[e], o);
    }
    __shared__ float sg[8][E_NUM];
    if ((tid & 31) == 0) {
        #pragma unroll
        for (int e = 0; e < E_NUM; e++) sg[tid >> 5][e] = ge[e];
    }
    __syncthreads();
    __shared__ float s_logit[E_NUM];
    if (tid < E_NUM) {
        float v = gb[tid];
        #pragma unroll
        for (int w = 0; w < 8; w++) v += sg[w][tid];
        s_logit[tid] = v;
    }
    __syncthreads();
    if (tid == 0) {
        float vals[E_NUM];
        #pragma unroll
        for (int e = 0; e < E_NUM; e++) vals[e] = s_logit[e];
        int ids[TOPK]; float tv[TOPK];
        #pragma unroll
        for (int k = 0; k < TOPK; k++) {
            int bi = 0; float bv = -1e30f;
            #pragma unroll
            for (int e = 0; e < E_NUM; e++) {
                if (vals[e] > bv) { bv = vals[e]; bi = e; }
            }
            ids[k] = bi; tv[k] = bv; vals[bi] = -1e30f;
        }
        float m = tv[0];
        float ex[TOPK]; float s = 0.f;
        #pragma unroll
        for (int k = 0; k < TOPK; k++) { ex[k] = expf(tv[k] - m); s += ex[k]; }
        float inv = 1.0f / s;
        #pragma unroll
        for (int k = 0; k < TOPK; k++) {
            g_topidx[t * TOPK + k] = ids[k];
            g_topw[t * TOPK + k]   = ex[k] * inv;
            atomicAdd(&g_cnt[ids[k]], 1);
        }
    }
}

// ---------------- 2: exclusive scan over 16 experts ----------------
__global__ void scan_kernel() {
    if (threadIdx.x == 0) {
        int acc = 0;
        for (int e = 0; e < E_NUM; e++) {
            g_off[e] = acc;
            acc += g_cnt[e];
            g_cnt2[e] = 0;
        }
    }
}

// ---------------- 3: scatter tokens into expert groups ----------------
__global__ void scatter_kernel() {
    int t = blockIdx.x * blockDim.x + threadIdx.x;
    if (t >= T_TOK) return;
    #pragma unroll
    for (int k = 0; k < TOPK; k++) {
        int e = g_topidx[t * TOPK + k];
        int pos = g_off[e] + atomicAdd(&g_cnt2[e], 1);
        g_rowtok[pos] = t;
        g_roww[pos]   = g_topw[t * TOPK + k];
        g_tokrows[t * TOPK + k] = pos;
    }
}

// ---------------- 4/5: grouped GEMMs (128x128x16 tiles, packed f32x2 FMA) ----------------
// MODE 1: A = gathered g_tnorm rows, B = mlp1_weight[e] ([2I,H] K-major), epilogue = swiglu -> g_h1
// MODE 2: A = g_h1 rows (already grouped), B = mlp2_weight[e] ([H,I] K-major), epilogue = *w -> g_h2
template <int MODE>
__global__ __launch_bounds__(256) void moe_gemm_kernel(
    const float* __restrict__ W, const float* __restrict__ bias)
{
    constexpr int BM = 128, BN = 128, BK = 16;
    constexpr int NTOT = (MODE == 1) ? 2 * I_DIM : H_DIM;
    constexpr int KDIM = (MODE == 1) ? H_DIM : I_DIM;

    // map blockIdx.y -> (expert, m-tile)
    int mt = blockIdx.y;
    int e = 0, acc = 0, cnt_e = 0, off_e = 0;
    bool found = false;
    #pragma unroll
    for (int ee = 0; ee < E_NUM; ee++) {
        int c = g_cnt[ee];
        int tl = (c + BM - 1) >> 7;
        if (!found && mt < acc + tl) {
            e = ee; cnt_e = c; off_e = g_off[ee]; found = true;
            mt -= acc;
        }
        if (!found) acc += tl;
    }
    if (!found) return;
    int m0  = mt * BM;
    int bn0 = blockIdx.x * BN;

    __shared__ float As[BK][BM];
    __shared__ float Bs[BK][BN];

    int tid = threadIdx.x;

    // per-thread load slots: 2 float4 for A, 2 float4 for B
    const float* abase[2];
    bool aval[2];
    int arow[2], akq[2];
    const float* bbase[2];
    int bcol[2], bkq[2];
    #pragma unroll
    for (int r = 0; r < 2; r++) {
        int f = tid + r * 256;
        int row = f >> 2;
        int kq  = (f & 3) * 4;
        arow[r] = row; akq[r] = kq;
        int lm = m0 + row;
        aval[r] = (lm < cnt_e);
        if (aval[r]) {
            if (MODE == 1) {
                int tok = g_rowtok[off_e + lm];
                abase[r] = g_tnorm + (size_t)tok * H_DIM + kq;
            } else {
                abase[r] = g_h1 + (size_t)(off_e + lm) * I_DIM + kq;
            }
        } else {
            abase[r] = g_tnorm;  // unused
        }
        bcol[r] = row; bkq[r] = kq;
        bbase[r] = W + ((size_t)e * NTOT + bn0 + row) * KDIM + kq;
    }

    int ty = tid >> 4;   // 0..15, rows m0 + ty*8 ..
    int tx = tid & 15;   // 0..15, cols bn0 + tx*8 ..

    unsigned long long cc[8][4];
    #pragma unroll
    for (int i = 0; i < 8; i++)
        #pragma unroll
        for (int j = 0; j < 4; j++) cc[i][j] = 0ull;

    for (int kt = 0; kt < KDIM / BK; kt++) {
        #pragma unroll
        for (int r = 0; r < 2; r++) {
            float4 va = make_float4(0.f, 0.f, 0.f, 0.f);
            if (aval[r]) va = *(const float4*)(abase[r] + kt * BK);
            As[akq[r] + 0][arow[r]] = va.x;
            As[akq[r] + 1][arow[r]] = va.y;
            As[akq[r] + 2][arow[r]] = va.z;
            As[akq[r] + 3][arow[r]] = va.w;
            float4 vb = *(const float4*)(bbase[r] + kt * BK);
            Bs[bkq[r] + 0][bcol[r]] = vb.x;
            Bs[bkq[r] + 1][bcol[r]] = vb.y;
            Bs[bkq[r] + 2][bcol[r]] = vb.z;
            Bs[bkq[r] + 3][bcol[r]] = vb.w;
        }
        __syncthreads();
        #pragma unroll
        for (int k = 0; k < BK; k++) {
            const float4* ap = (const float4*)&As[k][ty * 8];
            float4 a0 = ap[0], a1 = ap[1];
            const ulonglong2* bp = (const ulonglong2*)&Bs[k][tx * 8];
            ulonglong2 bb0 = bp[0], bb1 = bp[1];
            float av[8] = {a0.x, a0.y, a0.z, a0.w, a1.x, a1.y, a1.z, a1.w};
            unsigned long long bv[4] = {bb0.x, bb0.y, bb1.x, bb1.y};
            #pragma unroll
            for (int i = 0; i < 8; i++) {
                unsigned long long a2 = pk2(av[i], av[i]);
                #pragma unroll
                for (int j = 0; j < 4; j++) cc[i][j] = fma2(a2, bv[j], cc[i][j]);
            }
        }
        __syncthreads();
    }

    // epilogue
    #pragma unroll
    for (int i = 0; i < 8; i++) {
        int lm = m0 + ty * 8 + i;
        if (lm >= cnt_e) continue;
        int p = off_e + lm;
        if (MODE == 1) {
            #pragma unroll
            for (int j = 0; j < 4; j++) {
                int n = bn0 + tx * 8 + 2 * j;
                float lo, hi;
                upk2(cc[i][j], lo, hi);
                lo += bias[e * NTOT + n];
                hi += bias[e * NTOT + n + 1];
                lo = fminf(lo, 7.0f);                      // x_glu clip (max only)
                hi = fminf(fmaxf(hi, -7.0f), 7.0f);        // x_lin clip
                float sig = 1.0f / (1.0f + expf(-1.702f * lo));
                g_h1[(size_t)p * I_DIM + (n >> 1)] = lo * sig * (hi + 1.0f);
            }
        } else {
            float wgt = g_roww[p];
            #pragma unroll
            for (int j = 0; j < 4; j++) {
                int n = bn0 + tx * 8 + 2 * j;
                float lo, hi;
                upk2(cc[i][j], lo, hi);
                lo = (lo + bias[e * NTOT + n])     * wgt;
                hi = (hi + bias[e * NTOT + n + 1]) * wgt;
                *(float2*)&g_h2[(size_t)p * H_DIM + n] = make_float2(lo, hi);
            }
        }
    }
}

// ---------------- 6: combine (residual + 4 expert contributions) ----------------
__global__ __launch_bounds__(256) void combine_kernel(
    const float* __restrict__ x, float* __restrict__ out)
{
    int t = blockIdx.x;
    int tid = threadIdx.x;
    int p0 = g_tokrows[t * TOPK + 0];
    int p1 = g_tokrows[t * TOPK + 1];
    int p2 = g_tokrows[t * TOPK + 2];
    int p3 = g_tokrows[t * TOPK + 3];
    const float4* xr = (const float4*)(x + (size_t)t * H_DIM);
    float4* orow = (float4*)(out + (size_t)t * H_DIM);
    const float4* a = (const float4*)(g_h2 + (size_t)p0 * H_DIM);
    const float4* b = (const float4*)(g_h2 + (size_t)p1 * H_DIM);
    const float4* c = (const float4*)(g_h2 + (size_t)p2 * H_DIM);
    const float4* d = (const float4*)(g_h2 + (size_t)p3 * H_DIM);
    #pragma unroll
    for (int r = 0; r < 2; r++) {
        int f = tid + r * 256;
        float4 v = xr[f];
        float4 q0 = a[f], q1 = b[f], q2 = c[f], q3 = d[f];
        v.x += q0.x + q1.x + q2.x + q3.x;
        v.y += q0.y + q1.y + q2.y + q3.y;
        v.z += q0.z + q1.z + q2.z + q3.z;
        v.w += q0.w + q1.w + q2.w + q3.w;
        orow[f] = v;
    }
}

// ---------------- launch ----------------
extern "C" void kernel_launch(void* const* d_in, const int* in_sizes, int n_in,
                              void* d_out, int out_size)
{
    const float* x     = (const float*)d_in[0];
    const float* scale = (const float*)d_in[1];
    const float* gk    = (const float*)d_in[2];
    const float* gb    = (const float*)d_in[3];
    const float* w1    = (const float*)d_in[4];
    const float* b1    = (const float*)d_in[5];
    const float* w2    = (const float*)d_in[6];
    const float* b2    = (const float*)d_in[7];
    float* out = (float*)d_out;

    init_kernel<<<1, 32>>>();
    rms_router_kernel<<<T_TOK, 256>>>(x, scale, gk, gb);
    scan_kernel<<<1, 32>>>();
    scatter_kernel<<<(T_TOK + 255) / 256, 256>>>();
    // worst case M-tiles over all experts: 8192/128 + 15 <= 79 -> use 80
    moe_gemm_kernel<1><<<dim3(2 * I_DIM / 128, 80), 256>>>(w1, b1);
    moe_gemm_kernel<2><<<dim3(H_DIM / 128, 80), 256>>>(w2, b2);
    combine_kernel<<<T_TOK, 256>>>(x, out);
}

// round 3
// speedup vs baseline: 2.2451x; 2.2451x over previous
#include <cuda_runtime.h>
#include <cuda_bf16.h>
#include <math.h>
#include <stdint.h>

#define T_TOK 2048
#define H_DIM 2048
#define I_DIM 2048
#define E_NUM 16
#define TOPK  4
#define ROWS  (T_TOK*TOPK)

// ---------------- scratch ----------------
__device__ float g_tnorm[(size_t)T_TOK * H_DIM];   // 16 MB
__device__ float g_h1[(size_t)ROWS * I_DIM];       // 64 MB
__device__ float g_h2[(size_t)ROWS * H_DIM];       // 64 MB
__device__ int   g_cnt[E_NUM];
__device__ int   g_cnt2[E_NUM];
__device__ int   g_off[E_NUM];
__device__ int   g_rowtok[ROWS];
__device__ float g_roww[ROWS];
__device__ int   g_tokrows[T_TOK * TOPK];
__device__ int   g_topidx[T_TOK * TOPK];
__device__ float g_topw[T_TOK * TOPK];

// ---------------- PTX helpers (base compute_103 ISA only) ----------------
__device__ __forceinline__ uint32_t smem_u32(const void* p) {
    uint32_t a;
    asm("{ .reg .u64 t; cvta.to.shared.u64 t, %1; cvt.u32.u64 %0, t; }" : "=r"(a) : "l"(p));
    return a;
}
__device__ __forceinline__ void ldsm_x4(uint32_t* r, uint32_t addr) {
    asm volatile("ldmatrix.sync.aligned.m8n8.x4.shared.b16 {%0,%1,%2,%3}, [%4];"
                 : "=r"(r[0]), "=r"(r[1]), "=r"(r[2]), "=r"(r[3]) : "r"(addr));
}
__device__ __forceinline__ void ldsm_x2(uint32_t* r, uint32_t addr) {
    asm volatile("ldmatrix.sync.aligned.m8n8.x2.shared.b16 {%0,%1}, [%2];"
                 : "=r"(r[0]), "=r"(r[1]) : "r"(addr));
}
__device__ __forceinline__ void mma16816(float* d, const uint32_t* a, const uint32_t* b) {
    asm volatile("mma.sync.aligned.m16n8k16.row.col.f32.bf16.bf16.f32 "
                 "{%0,%1,%2,%3}, {%4,%5,%6,%7}, {%8,%9}, {%0,%1,%2,%3};"
                 : "+f"(d[0]), "+f"(d[1]), "+f"(d[2]), "+f"(d[3])
                 : "r"(a[0]), "r"(a[1]), "r"(a[2]), "r"(a[3]), "r"(b[0]), "r"(b[1]));
}
// split two fp32 -> packed bf16x2 hi and lo-residual
__device__ __forceinline__ void split2(float x0, float x1, uint32_t& hi, uint32_t& lo) {
    __nv_bfloat16 h0 = __float2bfloat16(x0), h1 = __float2bfloat16(x1);
    __nv_bfloat16 l0 = __float2bfloat16(x0 - __bfloat162float(h0));
    __nv_bfloat16 l1 = __float2bfloat16(x1 - __bfloat162float(h1));
    hi = (uint32_t)__bfloat16_as_ushort(h0) | ((uint32_t)__bfloat16_as_ushort(h1) << 16);
    lo = (uint32_t)__bfloat16_as_ushort(l0) | ((uint32_t)__bfloat16_as_ushort(l1) << 16);
}

// ---------------- 0: init ----------------
__global__ void init_kernel() {
    int i = threadIdx.x;
    if (i < E_NUM) { g_cnt[i] = 0; g_cnt2[i] = 0; }
}

// ---------------- 1: fused RMSNorm + router ----------------
__global__ __launch_bounds__(256) void rms_router_kernel(
    const float* __restrict__ x, const float* __restrict__ scale,
    const float* __restrict__ gk, const float* __restrict__ gb)
{
    int t = blockIdx.x;
    int tid = threadIdx.x;
    const float* xr = x + (size_t)t * H_DIM;

    float4 v0 = *(const float4*)(xr + tid * 8);
    float4 v1 = *(const float4*)(xr + tid * 8 + 4);
    float ss = v0.x*v0.x + v0.y*v0.y + v0.z*v0.z + v0.w*v0.w
             + v1.x*v1.x + v1.y*v1.y + v1.z*v1.z + v1.w*v1.w;
    #pragma unroll
    for (int o = 16; o > 0; o >>= 1) ss += __shfl_down_sync(0xffffffffu, ss, o);
    __shared__ float warpsum[8];
    __shared__ float s_r;
    if ((tid & 31) == 0) warpsum[tid >> 5] = ss;
    __syncthreads();
    if (tid == 0) {
        float tot = 0.f;
        #pragma unroll
        for (int w = 0; w < 8; w++) tot += warpsum[w];
        s_r = 1.0f / sqrtf(tot / (float)H_DIM + 1e-5f);
    }
    __syncthreads();
    float r = s_r;

    float4 sc0 = *(const float4*)(scale + tid * 8);
    float4 sc1 = *(const float4*)(scale + tid * 8 + 4);
    float tn[8];
    tn[0] = v0.x*r*sc0.x; tn[1] = v0.y*r*sc0.y; tn[2] = v0.z*r*sc0.z; tn[3] = v0.w*r*sc0.w;
    tn[4] = v1.x*r*sc1.x; tn[5] = v1.y*r*sc1.y; tn[6] = v1.z*r*sc1.z; tn[7] = v1.w*r*sc1.w;

    float* tr = g_tnorm + (size_t)t * H_DIM + tid * 8;
    *(float4*)(tr)     = make_float4(tn[0], tn[1], tn[2], tn[3]);
    *(float4*)(tr + 4) = make_float4(tn[4], tn[5], tn[6], tn[7]);

    float ge[E_NUM];
    #pragma unroll
    for (int e = 0; e < E_NUM; e++) ge[e] = 0.f;
    #pragma unroll
    for (int u = 0; u < 8; u++) {
        const float4* wrow = (const float4*)(gk + (size_t)(tid * 8 + u) * E_NUM);
        float tv = tn[u];
        float4 a = wrow[0], b = wrow[1], c = wrow[2], d = wrow[3];
        ge[0]+=tv*a.x; ge[1]+=tv*a.y; ge[2]+=tv*a.z; ge[3]+=tv*a.w;
        ge[4]+=tv*b.x; ge[5]+=tv*b.y; ge[6]+=tv*b.z; ge[7]+=tv*b.w;
        ge[8]+=tv*c.x; ge[9]+=tv*c.y; ge[10]+=tv*c.z; ge[11]+=tv*c.w;
        ge[12]+=tv*d.x; ge[13]+=tv*d.y; ge[14]+=tv*d.z; ge[15]+=tv*d.w;
    }
    #pragma unroll
    for (int o = 16; o > 0; o >>= 1) {
        #pragma unroll
        for (int e = 0; e < E_NUM; e++) ge[e] += __shfl_down_sync(0xffffffffu, ge[e], o);
    }
    __shared__ float sg[8][E_NUM];
    if ((tid & 31) == 0) {
        #pragma unroll
        for (int e = 0; e < E_NUM; e++) sg[tid >> 5][e] = ge[e];
    }
    __syncthreads();
    __shared__ float s_logit[E_NUM];
    if (tid < E_NUM) {
        float v = gb[tid];
        #pragma unroll
        for (int w = 0; w < 8; w++) v += sg[w][tid];
        s_logit[tid] = v;
    }
    __syncthreads();
    if (tid == 0) {
        float vals[E_NUM];
        #pragma unroll
        for (int e = 0; e < E_NUM; e++) vals[e] = s_logit[e];
        int ids[TOPK]; float tv[TOPK];
        #pragma unroll
        for (int k = 0; k < TOPK; k++) {
            int bi = 0; float bv = -1e30f;
            #pragma unroll
            for (int e = 0; e < E_NUM; e++) if (vals[e] > bv) { bv = vals[e]; bi = e; }
            ids[k] = bi; tv[k] = bv; vals[bi] = -1e30f;
        }
        float m = tv[0], ex[TOPK], s = 0.f;
        #pragma unroll
        for (int k = 0; k < TOPK; k++) { ex[k] = expf(tv[k] - m); s += ex[k]; }
        float inv = 1.0f / s;
        #pragma unroll
        for (int k = 0; k < TOPK; k++) {
            g_topidx[t * TOPK + k] = ids[k];
            g_topw[t * TOPK + k]   = ex[k] * inv;
            atomicAdd(&g_cnt[ids[k]], 1);
        }
    }
}

// ---------------- 2/3: scan + scatter ----------------
__global__ void scan_kernel() {
    if (threadIdx.x == 0) {
        int acc = 0;
        for (int e = 0; e < E_NUM; e++) { g_off[e] = acc; acc += g_cnt[e]; g_cnt2[e] = 0; }
    }
}
__global__ void scatter_kernel() {
    int t = blockIdx.x * blockDim.x + threadIdx.x;
    if (t >= T_TOK) return;
    #pragma unroll
    for (int k = 0; k < TOPK; k++) {
        int e = g_topidx[t * TOPK + k];
        int pos = g_off[e] + atomicAdd(&g_cnt2[e], 1);
        g_rowtok[pos] = t;
        g_roww[pos]   = g_topw[t * TOPK + k];
        g_tokrows[t * TOPK + k] = pos;
    }
}

// ---------------- 4/5: grouped GEMMs via mma.sync (bf16 3-term split) ----------------
// Tile 128x128x32.  8 warps in 2(m) x 4(n); warp tile 64x32.
// Smem rows padded to 80B (40 bf16) -> conflict-free ldmatrix.
#define ROWB 80
#define SM_AHI 0
#define SM_ALO 10240
#define SM_BHI 20480
#define SM_BLO 30720
#define SM_TOT 40960

template <int MODE>
__global__ __launch_bounds__(256) void moe_mma_kernel(
    const float* __restrict__ W, const float* __restrict__ bias)
{
    constexpr int NTOT = (MODE == 1) ? 2 * I_DIM : H_DIM;
    constexpr int KD = 2048;
    constexpr int NST = KD / 32;   // 64 stages

    // expert / m-tile mapping
    int mt = blockIdx.y;
    int e = -1, cnt_e = 0, off_e = 0, acc0 = 0;
    #pragma unroll
    for (int ee = 0; ee < E_NUM; ee++) {
        int c = g_cnt[ee];
        int tl = (c + 127) >> 7;
        if (e < 0) {
            if (mt < acc0 + tl) { e = ee; cnt_e = c; off_e = g_off[ee]; mt -= acc0; }
            else acc0 += tl;
        }
    }
    if (e < 0) return;
    int m0 = mt * 128;
    int bn0 = blockIdx.x * 128;

    __shared__ __align__(16) char sm[SM_TOT];
    uint32_t sbase = smem_u32(sm);

    int tid = threadIdx.x;
    int lane = tid & 31;
    int wid = tid >> 5;
    int wm = wid & 1;          // 0..1  (m 64-blocks)
    int wn = wid >> 1;         // 0..3  (n 32-blocks)

    // ---- per-thread LDG slots: 4 chunks of 16B (4 floats) each for A and B ----
    const float* aptr[4];
    const float* bptr[4];
    uint32_t stoff[4];
    #pragma unroll
    for (int t = 0; t < 4; t++) {
        int cid = tid + t * 256;            // 0..1023
        int row = cid >> 3;                 // 0..127
        int c16 = cid & 7;                  // 16B chunk within 128B row
        stoff[t] = (uint32_t)(row * ROWB + c16 * 8);
        int lm = m0 + row;
        int safe = (lm < cnt_e) ? lm : 0;
        if (MODE == 1) {
            int tok = g_rowtok[off_e + safe];
            aptr[t] = g_tnorm + (size_t)tok * KD + c16 * 4;
        } else {
            aptr[t] = g_h1 + (size_t)(off_e + safe) * KD + c16 * 4;
        }
        bptr[t] = W + ((size_t)e * NTOT + bn0 + row) * KD + c16 * 4;
    }

    // ldmatrix per-lane base offsets
    uint32_t aoff = (uint32_t)((wm * 64 + (lane & 15)) * ROWB + (lane >> 4) * 16);
    uint32_t boff = (uint32_t)((wn * 32 + (lane & 7)) * ROWB + ((lane >> 3) & 1) * 16);

    float acc[4][4][4];
    #pragma unroll
    for (int i = 0; i < 4; i++)
        #pragma unroll
        for (int j = 0; j < 4; j++)
            #pragma unroll
            for (int q = 0; q < 4; q++) acc[i][j][q] = 0.f;

    // prologue loads
    float4 rA[4], rB[4];
    #pragma unroll
    for (int t = 0; t < 4; t++) {
        rA[t] = *(const float4*)(aptr[t]);
        rB[t] = *(const float4*)(bptr[t]);
    }

    for (int kt = 0; kt < NST; kt++) {
        __syncthreads();
        #pragma unroll
        for (int t = 0; t < 4; t++) {
            uint32_t h0, l0, h1, l1;
            split2(rA[t].x, rA[t].y, h0, l0);
            split2(rA[t].z, rA[t].w, h1, l1);
            *(uint2*)(sm + SM_AHI + stoff[t]) = make_uint2(h0, h1);
            *(uint2*)(sm + SM_ALO + stoff[t]) = make_uint2(l0, l1);
            split2(rB[t].x, rB[t].y, h0, l0);
            split2(rB[t].z, rB[t].w, h1, l1);
            *(uint2*)(sm + SM_BHI + stoff[t]) = make_uint2(h0, h1);
            *(uint2*)(sm + SM_BLO + stoff[t]) = make_uint2(l0, l1);
        }
        __syncthreads();
        if (kt + 1 < NST) {
            #pragma unroll
            for (int t = 0; t < 4; t++) {
                rA[t] = *(const float4*)(aptr[t] + (kt + 1) * 32);
                rB[t] = *(const float4*)(bptr[t] + (kt + 1) * 32);
            }
        }
        #pragma unroll
        for (int ks = 0; ks < 2; ks++) {
            uint32_t ah[4][4], al[4][4];
            #pragma unroll
            for (int im = 0; im < 4; im++) {
                ldsm_x4(ah[im], sbase + SM_AHI + aoff + im * (16 * ROWB) + ks * 32);
                ldsm_x4(al[im], sbase + SM_ALO + aoff + im * (16 * ROWB) + ks * 32);
            }
            #pragma unroll
            for (int in = 0; in < 4; in++) {
                uint32_t bh[2], bl[2];
                ldsm_x2(bh, sbase + SM_BHI + boff + in * (8 * ROWB) + ks * 32);
                ldsm_x2(bl, sbase + SM_BLO + boff + in * (8 * ROWB) + ks * 32);
                #pragma unroll
                for (int im = 0; im < 4; im++) {
                    mma16816(acc[im][in], ah[im], bh);
                    mma16816(acc[im][in], al[im], bh);
                    mma16816(acc[im][in], ah[im], bl);
                }
            }
        }
    }

    // ---------------- epilogue ----------------
    #pragma unroll
    for (int im = 0; im < 4; im++) {
        #pragma unroll
        for (int in = 0; in < 4; in++) {
            int r0 = m0 + wm * 64 + im * 16 + (lane >> 2);
            int c  = bn0 + wn * 32 + in * 8 + (lane & 3) * 2;
            const float* bp = bias + (size_t)e * NTOT + c;
            #pragma unroll
            for (int half = 0; half < 2; half++) {
                int r = r0 + half * 8;
                if (r >= cnt_e) continue;
                int p = off_e + r;
                float d0 = acc[im][in][half * 2 + 0];
                float d1 = acc[im][in][half * 2 + 1];
                if (MODE == 1) {
                    float glu = d0 + __ldg(bp);
                    float lin = d1 + __ldg(bp + 1);
                    glu = fminf(glu, 7.0f);
                    lin = fminf(fmaxf(lin, -7.0f), 7.0f);
                    float sig = 1.0f / (1.0f + expf(-1.702f * glu));
                    g_h1[(size_t)p * I_DIM + (c >> 1)] = glu * sig * (lin + 1.0f);
                } else {
                    float w = g_roww[p];
                    float o0 = (d0 + __ldg(bp)) * w;
                    float o1 = (d1 + __ldg(bp + 1)) * w;
                    *(float2*)&g_h2[(size_t)p * H_DIM + c] = make_float2(o0, o1);
                }
            }
        }
    }
}

// ---------------- 6: combine ----------------
__global__ __launch_bounds__(256) void combine_kernel(
    const float* __restrict__ x, float* __restrict__ out)
{
    int t = blockIdx.x;
    int tid = threadIdx.x;
    int p0 = g_tokrows[t * TOPK + 0];
    int p1 = g_tokrows[t * TOPK + 1];
    int p2 = g_tokrows[t * TOPK + 2];
    int p3 = g_tokrows[t * TOPK + 3];
    const float4* xr = (const float4*)(x + (size_t)t * H_DIM);
    float4* orow = (float4*)(out + (size_t)t * H_DIM);
    const float4* a = (const float4*)(g_h2 + (size_t)p0 * H_DIM);
    const float4* b = (const float4*)(g_h2 + (size_t)p1 * H_DIM);
    const float4* c = (const float4*)(g_h2 + (size_t)p2 * H_DIM);
    const float4* d = (const float4*)(g_h2 + (size_t)p3 * H_DIM);
    #pragma unroll
    for (int r = 0; r < 2; r++) {
        int f = tid + r * 256;
        float4 v = xr[f];
        float4 q0 = a[f], q1 = b[f], q2 = c[f], q3 = d[f];
        v.x += q0.x + q1.x + q2.x + q3.x;
        v.y += q0.y + q1.y + q2.y + q3.y;
        v.z += q0.z + q1.z + q2.z + q3.z;
        v.w += q0.w + q1.w + q2.w + q3.w;
        orow[f] = v;
    }
}

// ---------------- launch ----------------
extern "C" void kernel_launch(void* const* d_in, const int* in_sizes, int n_in,
                              void* d_out, int out_size)
{
    const float* x     = (const float*)d_in[0];
    const float* scale = (const float*)d_in[1];
    const float* gk    = (const float*)d_in[2];
    const float* gb    = (const float*)d_in[3];
    const float* w1    = (const float*)d_in[4];
    const float* b1    = (const float*)d_in[5];
    const float* w2    = (const float*)d_in[6];
    const float* b2    = (const float*)d_in[7];
    float* out = (float*)d_out;

    init_kernel<<<1, 32>>>();
    rms_router_kernel<<<T_TOK, 256>>>(x, scale, gk, gb);
    scan_kernel<<<1, 32>>>();
    scatter_kernel<<<(T_TOK + 255) / 256, 256>>>();
    moe_mma_kernel<1><<<dim3(2 * I_DIM / 128, 80), 256>>>(w1, b1);
    moe_mma_kernel<2><<<dim3(H_DIM / 128, 80), 256>>>(w2, b2);
    combine_kernel<<<T_TOK, 256>>>(x, out);
}